// round 1
// baseline (speedup 1.0000x reference)
#include <cuda_runtime.h>
#include <cuda_bf16.h>
#include <math.h>

// ----------------------------------------------------------------------------
// Problem constants (fixed shapes)
// ----------------------------------------------------------------------------
#define BB   4
#define TT   1024
#define SS   4096
#define DD   1024
#define HH   16
#define HD   64

__constant__ int c_stride[HH] = {1,2,4,8, 1,2,4,8, 1,2,4,8, 1,2,4,8};

// Scratch (device globals are the allowed scratch mechanism)
__device__ float g_Q[(size_t)BB * TT * DD];      // 16 MB
__device__ float g_K[(size_t)BB * SS * DD];      // 64 MB
__device__ float g_V[(size_t)BB * SS * DD];      // 64 MB
__device__ float g_attn[(size_t)BB * TT * DD];   // 16 MB

// ----------------------------------------------------------------------------
// GEMM:  C[M,N] = A[M,K] @ W[N,K]^T + bias[N]
// A row-major [M,K], W row-major [N,K]  (both K-contiguous -> NT GEMM)
// BM=BN=128, BK=16, 256 threads, 8x8 micro-tile
// ----------------------------------------------------------------------------
#define BM 128
#define BN 128
#define BK 16

__global__ __launch_bounds__(256, 2)
void gemm_nt_bias_kernel(const float* __restrict__ A,
                         const float* __restrict__ W,
                         const float* __restrict__ bias,
                         float* __restrict__ C,
                         int M, int N, int K)
{
    __shared__ float As[BK][BM];
    __shared__ float Ws[BK][BN];

    const int tid = threadIdx.x;
    const int tx  = tid & 15;         // 0..15 -> N micro
    const int ty  = tid >> 4;         // 0..15 -> M micro

    const int row0 = blockIdx.y * BM;
    const int col0 = blockIdx.x * BN;

    // loader mapping: 256 threads, each loads 2 float4 from A and 2 from W / tile
    const int lr  = tid >> 2;         // 0..63 (row within tile, +64 second pass)
    const int lc4 = tid & 3;          // which float4 of the 16 k-floats

    float acc[8][8];
#pragma unroll
    for (int i = 0; i < 8; ++i)
#pragma unroll
        for (int j = 0; j < 8; ++j) acc[i][j] = 0.f;

    for (int k0 = 0; k0 < K; k0 += BK) {
#pragma unroll
        for (int p = 0; p < 2; ++p) {
            const int r = lr + p * 64;
            float4 va = *(const float4*)&A[(size_t)(row0 + r) * K + k0 + lc4 * 4];
            As[lc4 * 4 + 0][r] = va.x;
            As[lc4 * 4 + 1][r] = va.y;
            As[lc4 * 4 + 2][r] = va.z;
            As[lc4 * 4 + 3][r] = va.w;
            float4 vw = *(const float4*)&W[(size_t)(col0 + r) * K + k0 + lc4 * 4];
            Ws[lc4 * 4 + 0][r] = vw.x;
            Ws[lc4 * 4 + 1][r] = vw.y;
            Ws[lc4 * 4 + 2][r] = vw.z;
            Ws[lc4 * 4 + 3][r] = vw.w;
        }
        __syncthreads();

#pragma unroll
        for (int kk = 0; kk < BK; ++kk) {
            float4 a0 = *(const float4*)&As[kk][ty * 8];
            float4 a1 = *(const float4*)&As[kk][ty * 8 + 4];
            float4 b0 = *(const float4*)&Ws[kk][tx * 8];
            float4 b1 = *(const float4*)&Ws[kk][tx * 8 + 4];
            const float ra[8] = {a0.x, a0.y, a0.z, a0.w, a1.x, a1.y, a1.z, a1.w};
            const float rb[8] = {b0.x, b0.y, b0.z, b0.w, b1.x, b1.y, b1.z, b1.w};
#pragma unroll
            for (int i = 0; i < 8; ++i)
#pragma unroll
                for (int j = 0; j < 8; ++j)
                    acc[i][j] = fmaf(ra[i], rb[j], acc[i][j]);
        }
        __syncthreads();
    }

    // epilogue with bias
    const float4 bv0 = *(const float4*)&bias[col0 + tx * 8];
    const float4 bv1 = *(const float4*)&bias[col0 + tx * 8 + 4];
    const float rb0[8] = {bv0.x, bv0.y, bv0.z, bv0.w, bv1.x, bv1.y, bv1.z, bv1.w};
#pragma unroll
    for (int i = 0; i < 8; ++i) {
        float* crow = &C[(size_t)(row0 + ty * 8 + i) * N + col0 + tx * 8];
        float4 o0, o1;
        o0.x = acc[i][0] + rb0[0]; o0.y = acc[i][1] + rb0[1];
        o0.z = acc[i][2] + rb0[2]; o0.w = acc[i][3] + rb0[3];
        o1.x = acc[i][4] + rb0[4]; o1.y = acc[i][5] + rb0[5];
        o1.z = acc[i][6] + rb0[6]; o1.w = acc[i][7] + rb0[7];
        *(float4*)(crow)     = o0;
        *(float4*)(crow + 4) = o1;
    }
}

// ----------------------------------------------------------------------------
// Flash attention with per-head strided K/V.
// grid: (T/64, B*H), block: 256 (16x16). Each CTA: 64 queries x full S_h.
// smem layout (dynamic, 64 KB):
//   Qt[64][64]  d-major  (Qt[d][r] = Q[r][d])
//   Kt[64][64]  d-major
//   Vs[64][64]  row-major (Vs[c][d])
//   Pt[64][64]  c-major transposed P (Pt[c][r])
// ----------------------------------------------------------------------------
__global__ __launch_bounds__(256, 3)
void flash_attn_kernel(const float* __restrict__ Q,
                       const float* __restrict__ K,
                       const float* __restrict__ V,
                       float* __restrict__ O)
{
    extern __shared__ float sm[];
    float* Qt = sm;                 // 4096
    float* Kt = sm + 4096;          // 4096
    float* Vs = sm + 8192;          // 4096
    float* Pt = sm + 12288;         // 4096

    const int tid = threadIdx.x;
    const int tx  = tid & 15;
    const int ty  = tid >> 4;

    const int bh = blockIdx.y;
    const int b  = bh >> 4;
    const int h  = bh & 15;
    const int stride = c_stride[h];
    const int Sh = SS / stride;
    const int t0 = blockIdx.x * 64;
    const float scale = 0.125f;   // 1/sqrt(64)

    // ---- load Q tile transposed: Qt[d][r] ----
    const int r  = tid & 63;      // row within tile
    const int d4 = tid >> 6;      // 0..3
    {
        const float* qb = Q + (size_t)(b * TT + t0 + r) * DD + h * HD;
#pragma unroll
        for (int p = 0; p < 4; ++p) {
            const int dd = (d4 + p * 4) * 4;
            float4 v = *(const float4*)(qb + dd);
            Qt[(dd + 0) * 64 + r] = v.x;
            Qt[(dd + 1) * 64 + r] = v.y;
            Qt[(dd + 2) * 64 + r] = v.z;
            Qt[(dd + 3) * 64 + r] = v.w;
        }
    }

    float m_i[4], l_i[4], acc[4][4];
#pragma unroll
    for (int i = 0; i < 4; ++i) {
        m_i[i] = -INFINITY;
        l_i[i] = 0.f;
#pragma unroll
        for (int j = 0; j < 4; ++j) acc[i][j] = 0.f;
    }

    const int nTiles = Sh >> 6;
    for (int tile = 0; tile < nTiles; ++tile) {
        // ---- load K tile (d-major) and V tile (row-major), strided rows ----
        {
            const int srow = (tile * 64 + r) * stride;
            const float* kb = K + (size_t)(b * SS + srow) * DD + h * HD;
            const float* vb = V + (size_t)(b * SS + srow) * DD + h * HD;
#pragma unroll
            for (int p = 0; p < 4; ++p) {
                const int dd = (d4 + p * 4) * 4;
                float4 kv = *(const float4*)(kb + dd);
                Kt[(dd + 0) * 64 + r] = kv.x;
                Kt[(dd + 1) * 64 + r] = kv.y;
                Kt[(dd + 2) * 64 + r] = kv.z;
                Kt[(dd + 3) * 64 + r] = kv.w;
                float4 vv = *(const float4*)(vb + dd);
                *(float4*)&Vs[r * 64 + dd] = vv;
            }
        }
        __syncthreads();

        // ---- scores: s[i][j] = sum_d Qt[d][ty*4+i] * Kt[d][tx*4+j] ----
        float s[4][4];
#pragma unroll
        for (int i = 0; i < 4; ++i)
#pragma unroll
            for (int j = 0; j < 4; ++j) s[i][j] = 0.f;

#pragma unroll
        for (int d = 0; d < 64; ++d) {
            float4 qa = *(const float4*)&Qt[d * 64 + ty * 4];
            float4 kb4 = *(const float4*)&Kt[d * 64 + tx * 4];
            const float ra[4] = {qa.x, qa.y, qa.z, qa.w};
            const float rb[4] = {kb4.x, kb4.y, kb4.z, kb4.w};
#pragma unroll
            for (int i = 0; i < 4; ++i)
#pragma unroll
                for (int j = 0; j < 4; ++j)
                    s[i][j] = fmaf(ra[i], rb[j], s[i][j]);
        }

        // ---- online softmax ----
        float rmax[4], rsum[4], mnew[4], corr[4];
#pragma unroll
        for (int i = 0; i < 4; ++i) {
            float mx = s[i][0] * scale;
            mx = fmaxf(mx, s[i][1] * scale);
            mx = fmaxf(mx, s[i][2] * scale);
            mx = fmaxf(mx, s[i][3] * scale);
            rmax[i] = mx;
        }
#pragma unroll
        for (int msk = 1; msk < 16; msk <<= 1)
#pragma unroll
            for (int i = 0; i < 4; ++i)
                rmax[i] = fmaxf(rmax[i], __shfl_xor_sync(0xffffffffu, rmax[i], msk));

#pragma unroll
        for (int i = 0; i < 4; ++i) {
            mnew[i] = fmaxf(m_i[i], rmax[i]);
            corr[i] = __expf(m_i[i] - mnew[i]);   // 0 on first tile
            m_i[i]  = mnew[i];
        }

        float p[4][4];
#pragma unroll
        for (int i = 0; i < 4; ++i) {
            float su = 0.f;
#pragma unroll
            for (int j = 0; j < 4; ++j) {
                p[i][j] = __expf(fmaf(s[i][j], scale, -mnew[i]));
                su += p[i][j];
            }
            rsum[i] = su;
        }
#pragma unroll
        for (int msk = 1; msk < 16; msk <<= 1)
#pragma unroll
            for (int i = 0; i < 4; ++i)
                rsum[i] += __shfl_xor_sync(0xffffffffu, rsum[i], msk);

#pragma unroll
        for (int i = 0; i < 4; ++i) {
            l_i[i] = l_i[i] * corr[i] + rsum[i];
#pragma unroll
            for (int j = 0; j < 4; ++j) acc[i][j] *= corr[i];
        }

        // ---- write P transposed: Pt[c][r] ----
#pragma unroll
        for (int j = 0; j < 4; ++j)
#pragma unroll
            for (int i = 0; i < 4; ++i)
                Pt[(tx * 4 + j) * 64 + ty * 4 + i] = p[i][j];
        __syncthreads();

        // ---- PV: acc[i][j] += sum_c Pt[c][ty*4+i] * Vs[c][tx*4+j] ----
#pragma unroll
        for (int c = 0; c < 64; ++c) {
            float4 pa = *(const float4*)&Pt[c * 64 + ty * 4];
            float4 vv = *(const float4*)&Vs[c * 64 + tx * 4];
            const float ra[4] = {pa.x, pa.y, pa.z, pa.w};
            const float rb[4] = {vv.x, vv.y, vv.z, vv.w};
#pragma unroll
            for (int i = 0; i < 4; ++i)
#pragma unroll
                for (int j = 0; j < 4; ++j)
                    acc[i][j] = fmaf(ra[i], rb[j], acc[i][j]);
        }
        __syncthreads();   // before next tile overwrites Kt/Vs/Pt
    }

    // ---- epilogue: O[b, t0+row, h*64+col] = acc / l ----
#pragma unroll
    for (int i = 0; i < 4; ++i) {
        const float inv = 1.0f / l_i[i];
        float* orow = O + (size_t)(b * TT + t0 + ty * 4 + i) * DD + h * HD + tx * 4;
        float4 o;
        o.x = acc[i][0] * inv;
        o.y = acc[i][1] * inv;
        o.z = acc[i][2] * inv;
        o.w = acc[i][3] * inv;
        *(float4*)orow = o;
    }
}

// ----------------------------------------------------------------------------
// Launch
// ----------------------------------------------------------------------------
extern "C" void kernel_launch(void* const* d_in, const int* in_sizes, int n_in,
                              void* d_out, int out_size)
{
    const float* dec = (const float*)d_in[0];   // [B,T,D]
    const float* enc = (const float*)d_in[1];   // [B,S,D]
    const float* Wq  = (const float*)d_in[2];
    const float* bq  = (const float*)d_in[3];
    const float* Wk  = (const float*)d_in[4];
    const float* bk  = (const float*)d_in[5];
    const float* Wv  = (const float*)d_in[6];
    const float* bv  = (const float*)d_in[7];
    const float* Wo  = (const float*)d_in[8];
    const float* bo  = (const float*)d_in[9];
    float* out = (float*)d_out;

    float *gQ, *gK, *gV, *gA;
    cudaGetSymbolAddress((void**)&gQ, g_Q);
    cudaGetSymbolAddress((void**)&gK, g_K);
    cudaGetSymbolAddress((void**)&gV, g_V);
    cudaGetSymbolAddress((void**)&gA, g_attn);

    // flash kernel needs 64 KB dynamic smem
    static const int SMEM_BYTES = 4 * 64 * 64 * (int)sizeof(float);
    cudaFuncSetAttribute(flash_attn_kernel,
                         cudaFuncAttributeMaxDynamicSharedMemorySize, SMEM_BYTES);

    // Q projection: [B*T, D] = dec @ Wq^T + bq
    {
        dim3 grid(DD / BN, (BB * TT) / BM);
        gemm_nt_bias_kernel<<<grid, 256>>>(dec, Wq, bq, gQ, BB * TT, DD, DD);
    }
    // K projection: [B*S, D]
    {
        dim3 grid(DD / BN, (BB * SS) / BM);
        gemm_nt_bias_kernel<<<grid, 256>>>(enc, Wk, bk, gK, BB * SS, DD, DD);
    }
    // V projection: [B*S, D]
    {
        dim3 grid(DD / BN, (BB * SS) / BM);
        gemm_nt_bias_kernel<<<grid, 256>>>(enc, Wv, bv, gV, BB * SS, DD, DD);
    }
    // Attention
    {
        dim3 grid(TT / 64, BB * HH);
        flash_attn_kernel<<<grid, 256, SMEM_BYTES>>>(gQ, gK, gV, gA);
    }
    // Output projection: [B*T, D] = attn @ Wo^T + bo
    {
        dim3 grid(DD / BN, (BB * TT) / BM);
        gemm_nt_bias_kernel<<<grid, 256>>>(gA, Wo, bo, out, BB * TT, DD, DD);
    }
}

// round 3
// speedup vs baseline: 1.6253x; 1.6253x over previous
#include <cuda_runtime.h>
#include <cuda_bf16.h>
#include <math.h>
#include <stdint.h>

// ----------------------------------------------------------------------------
// Problem constants (fixed shapes)
// ----------------------------------------------------------------------------
#define BB   4
#define TT   1024
#define SS   4096
#define DD   1024
#define HH   16
#define HD   64

__constant__ int c_stride[HH] = {1,2,4,8, 1,2,4,8, 1,2,4,8, 1,2,4,8};

// Scratch (device globals are the allowed scratch mechanism)
__device__ float g_Q[(size_t)BB * TT * DD];      // 16 MB
__device__ float g_K[(size_t)BB * SS * DD];      // 64 MB
__device__ float g_V[(size_t)BB * SS * DD];      // 64 MB
__device__ float g_attn[(size_t)BB * TT * DD];   // 16 MB

// ----------------------------------------------------------------------------
// Helpers (sm_100 baseline features only — NO 'a'-suffix instructions)
// ----------------------------------------------------------------------------
__device__ __forceinline__ uint32_t smem_u32(const void* p) {
    uint32_t a;
    asm("{ .reg .u64 t; cvta.to.shared.u64 t, %1; cvt.u32.u64 %0, t; }"
        : "=r"(a) : "l"(p));
    return a;
}
__device__ __forceinline__ uint32_t f2tf32(float x) {
    uint32_t o;
    asm("cvt.rna.tf32.f32 %0, %1;" : "=r"(o) : "f"(x));
    return o;
}
__device__ __forceinline__ void ldmatrix_x4(uint32_t* f, uint32_t addr) {
    asm volatile("ldmatrix.sync.aligned.m8n8.x4.shared.b16 {%0,%1,%2,%3}, [%4];"
                 : "=r"(f[0]), "=r"(f[1]), "=r"(f[2]), "=r"(f[3]) : "r"(addr));
}
__device__ __forceinline__ void mma_tf32(float* c, const uint32_t* a,
                                         uint32_t b0, uint32_t b1) {
    asm volatile(
        "mma.sync.aligned.m16n8k8.row.col.f32.tf32.tf32.f32 "
        "{%0,%1,%2,%3}, {%4,%5,%6,%7}, {%8,%9}, {%0,%1,%2,%3};"
        : "+f"(c[0]), "+f"(c[1]), "+f"(c[2]), "+f"(c[3])
        : "r"(a[0]), "r"(a[1]), "r"(a[2]), "r"(a[3]), "r"(b0), "r"(b1));
}

// ----------------------------------------------------------------------------
// Tensor-core tf32 GEMM:  C[M,N] = A[M,K] @ W[N,K]^T + bias[N]
// CTA tile 128x128, BK=32 (128B rows), 8 warps 2(m)x4(n), warp tile 64x32.
// Smem tiles: 128 rows x 32 tf32 (128B/row), XOR swizzle on 16B segments.
// Double buffered (2 x 32KB).
// ----------------------------------------------------------------------------
#define GM_BM 128
#define GM_BN 128
#define GM_BK 32
#define GM_TILE_BYTES  (128 * 128)               // one 128x32 f32 tile = 16KB
#define GM_STAGE_BYTES (2 * GM_TILE_BYTES)       // A + B = 32KB
#define GM_SMEM_BYTES  (2 * GM_STAGE_BYTES)      // 64KB

// byte offset of (row, 16B-segment) inside a tile, with conflict-free swizzle
static __device__ __forceinline__ uint32_t tile_off(int row, int seg) {
    return (uint32_t)(row * 128 + ((seg ^ (row & 7)) << 4));
}

__global__ __launch_bounds__(256)
void gemm_tc_tf32_kernel(const float* __restrict__ A,
                         const float* __restrict__ W,
                         const float* __restrict__ bias,
                         float* __restrict__ C,
                         int M, int N, int K)
{
    extern __shared__ char sm_raw[];
    const uint32_t smBase = smem_u32(sm_raw);

    const int tid  = threadIdx.x;
    const int wid  = tid >> 5;
    const int lane = tid & 31;

    const int row0 = blockIdx.y * GM_BM;
    const int col0 = blockIdx.x * GM_BN;

    const int warp_m0 = (wid >> 2) * 64;   // 0 or 64
    const int warp_n0 = (wid & 3) * 32;    // 0,32,64,96

    // ldmatrix lane addressing pattern (same for A and B tiles)
    const int rrow = (lane & 7) + (((lane >> 3) & 1) << 3);  // row within 16-block
    const int sadd = lane >> 4;                              // 0 or 1 (16B seg)

    const float* Ap = A + (size_t)row0 * K;
    const float* Wp = W + (size_t)col0 * K;

    float acc[4][4][4];
#pragma unroll
    for (int i = 0; i < 4; ++i)
#pragma unroll
        for (int j = 0; j < 4; ++j)
#pragma unroll
            for (int q = 0; q < 4; ++q) acc[i][j][q] = 0.f;

    // loader indices: 256 threads x 4 iters -> 1024 (row,seg) pairs per tile
    const int l_row[4] = { (tid + 0)   >> 3, (tid + 256) >> 3,
                           (tid + 512) >> 3, (tid + 768) >> 3 };
    const int l_seg = tid & 7;

    auto sts_tile = [&](uint32_t tbase, const float4* r) {
#pragma unroll
        for (int it = 0; it < 4; ++it) {
            uint4 u;
            u.x = f2tf32(r[it].x); u.y = f2tf32(r[it].y);
            u.z = f2tf32(r[it].z); u.w = f2tf32(r[it].w);
            *(uint4*)(sm_raw + (tbase - smBase) + tile_off(l_row[it], l_seg)) = u;
        }
    };
    auto ldg_tile = [&](const float* g, int k0, float4* r) {
#pragma unroll
        for (int it = 0; it < 4; ++it)
            r[it] = *(const float4*)(g + (size_t)l_row[it] * K + k0 + l_seg * 4);
    };

    const int NCH = K / GM_BK;

    // prologue: chunk 0 -> stage 0
    {
        float4 rA[4], rB[4];
        ldg_tile(Ap, 0, rA);
        ldg_tile(Wp, 0, rB);
        sts_tile(smBase, rA);
        sts_tile(smBase + GM_TILE_BYTES, rB);
    }
    __syncthreads();

    for (int c = 0; c < NCH; ++c) {
        const int s = c & 1;
        const uint32_t aBase = smBase + s * GM_STAGE_BYTES;
        const uint32_t bBase = aBase + GM_TILE_BYTES;

        float4 rA[4], rB[4];
        const bool pref = (c + 1 < NCH);
        if (pref) {
            ldg_tile(Ap, (c + 1) * GM_BK, rA);
            ldg_tile(Wp, (c + 1) * GM_BK, rB);
        }

        // compute current stage: 4 k8-steps
#pragma unroll
        for (int k = 0; k < 4; ++k) {
            const int seg = k * 2 + sadd;
            uint32_t af[4][4], bf[2][4];
#pragma unroll
            for (int i = 0; i < 4; ++i) {
                const int row = warp_m0 + 16 * i + rrow;
                ldmatrix_x4(af[i], aBase + tile_off(row, seg));
            }
#pragma unroll
            for (int j = 0; j < 2; ++j) {
                const int row = warp_n0 + 16 * j + rrow;
                ldmatrix_x4(bf[j], bBase + tile_off(row, seg));
            }
#pragma unroll
            for (int i = 0; i < 4; ++i)
#pragma unroll
                for (int j = 0; j < 2; ++j) {
                    mma_tf32(acc[i][2 * j],     af[i], bf[j][0], bf[j][2]);
                    mma_tf32(acc[i][2 * j + 1], af[i], bf[j][1], bf[j][3]);
                }
        }

        if (pref) {
            const uint32_t a2 = smBase + (s ^ 1) * GM_STAGE_BYTES;
            sts_tile(a2, rA);
            sts_tile(a2 + GM_TILE_BYTES, rB);
        }
        __syncthreads();
    }

    // epilogue: c0,c1 -> (row=g, col=2t,2t+1); c2,c3 -> row=g+8
    {
        const int g = lane >> 2;
        const int t = lane & 3;
#pragma unroll
        for (int i = 0; i < 4; ++i) {
            const int r = row0 + warp_m0 + 16 * i + g;
#pragma unroll
            for (int jb = 0; jb < 4; ++jb) {
                const int cc = col0 + warp_n0 + 8 * jb + 2 * t;
                const float bx = __ldg(&bias[cc]);
                const float by = __ldg(&bias[cc + 1]);
                *(float2*)&C[(size_t)r * N + cc] =
                    make_float2(acc[i][jb][0] + bx, acc[i][jb][1] + by);
                *(float2*)&C[(size_t)(r + 8) * N + cc] =
                    make_float2(acc[i][jb][2] + bx, acc[i][jb][3] + by);
            }
        }
    }
}

// ----------------------------------------------------------------------------
// Flash attention with per-head strided K/V (SIMT, unchanged — passed R1).
// grid: (T/64, B*H), block: 256 (16x16).
// ----------------------------------------------------------------------------
__global__ __launch_bounds__(256, 3)
void flash_attn_kernel(const float* __restrict__ Q,
                       const float* __restrict__ K,
                       const float* __restrict__ V,
                       float* __restrict__ O)
{
    extern __shared__ float sm[];
    float* Qt = sm;                 // 4096
    float* Kt = sm + 4096;          // 4096
    float* Vs = sm + 8192;          // 4096
    float* Pt = sm + 12288;         // 4096

    const int tid = threadIdx.x;
    const int tx  = tid & 15;
    const int ty  = tid >> 4;

    const int bh = blockIdx.y;
    const int b  = bh >> 4;
    const int h  = bh & 15;
    const int stride = c_stride[h];
    const int Sh = SS / stride;
    const int t0 = blockIdx.x * 64;
    const float scale = 0.125f;   // 1/sqrt(64)

    const int r  = tid & 63;
    const int d4 = tid >> 6;
    {
        const float* qb = Q + (size_t)(b * TT + t0 + r) * DD + h * HD;
#pragma unroll
        for (int p = 0; p < 4; ++p) {
            const int dd = (d4 + p * 4) * 4;
            float4 v = *(const float4*)(qb + dd);
            Qt[(dd + 0) * 64 + r] = v.x;
            Qt[(dd + 1) * 64 + r] = v.y;
            Qt[(dd + 2) * 64 + r] = v.z;
            Qt[(dd + 3) * 64 + r] = v.w;
        }
    }

    float m_i[4], l_i[4], acc[4][4];
#pragma unroll
    for (int i = 0; i < 4; ++i) {
        m_i[i] = -INFINITY;
        l_i[i] = 0.f;
#pragma unroll
        for (int j = 0; j < 4; ++j) acc[i][j] = 0.f;
    }

    const int nTiles = Sh >> 6;
    for (int tile = 0; tile < nTiles; ++tile) {
        {
            const int srow = (tile * 64 + r) * stride;
            const float* kb = K + (size_t)(b * SS + srow) * DD + h * HD;
            const float* vb = V + (size_t)(b * SS + srow) * DD + h * HD;
#pragma unroll
            for (int p = 0; p < 4; ++p) {
                const int dd = (d4 + p * 4) * 4;
                float4 kv = *(const float4*)(kb + dd);
                Kt[(dd + 0) * 64 + r] = kv.x;
                Kt[(dd + 1) * 64 + r] = kv.y;
                Kt[(dd + 2) * 64 + r] = kv.z;
                Kt[(dd + 3) * 64 + r] = kv.w;
                float4 vv = *(const float4*)(vb + dd);
                *(float4*)&Vs[r * 64 + dd] = vv;
            }
        }
        __syncthreads();

        float s[4][4];
#pragma unroll
        for (int i = 0; i < 4; ++i)
#pragma unroll
            for (int j = 0; j < 4; ++j) s[i][j] = 0.f;

#pragma unroll
        for (int d = 0; d < 64; ++d) {
            float4 qa = *(const float4*)&Qt[d * 64 + ty * 4];
            float4 kb4 = *(const float4*)&Kt[d * 64 + tx * 4];
            const float ra[4] = {qa.x, qa.y, qa.z, qa.w};
            const float rb[4] = {kb4.x, kb4.y, kb4.z, kb4.w};
#pragma unroll
            for (int i = 0; i < 4; ++i)
#pragma unroll
                for (int j = 0; j < 4; ++j)
                    s[i][j] = fmaf(ra[i], rb[j], s[i][j]);
        }

        float rmax[4], rsum[4], mnew[4], corr[4];
#pragma unroll
        for (int i = 0; i < 4; ++i) {
            float mx = s[i][0] * scale;
            mx = fmaxf(mx, s[i][1] * scale);
            mx = fmaxf(mx, s[i][2] * scale);
            mx = fmaxf(mx, s[i][3] * scale);
            rmax[i] = mx;
        }
#pragma unroll
        for (int msk = 1; msk < 16; msk <<= 1)
#pragma unroll
            for (int i = 0; i < 4; ++i)
                rmax[i] = fmaxf(rmax[i], __shfl_xor_sync(0xffffffffu, rmax[i], msk));

#pragma unroll
        for (int i = 0; i < 4; ++i) {
            mnew[i] = fmaxf(m_i[i], rmax[i]);
            corr[i] = __expf(m_i[i] - mnew[i]);
            m_i[i]  = mnew[i];
        }

        float p[4][4];
#pragma unroll
        for (int i = 0; i < 4; ++i) {
            float su = 0.f;
#pragma unroll
            for (int j = 0; j < 4; ++j) {
                p[i][j] = __expf(fmaf(s[i][j], scale, -mnew[i]));
                su += p[i][j];
            }
            rsum[i] = su;
        }
#pragma unroll
        for (int msk = 1; msk < 16; msk <<= 1)
#pragma unroll
            for (int i = 0; i < 4; ++i)
                rsum[i] += __shfl_xor_sync(0xffffffffu, rsum[i], msk);

#pragma unroll
        for (int i = 0; i < 4; ++i) {
            l_i[i] = l_i[i] * corr[i] + rsum[i];
#pragma unroll
            for (int j = 0; j < 4; ++j) acc[i][j] *= corr[i];
        }

#pragma unroll
        for (int j = 0; j < 4; ++j)
#pragma unroll
            for (int i = 0; i < 4; ++i)
                Pt[(tx * 4 + j) * 64 + ty * 4 + i] = p[i][j];
        __syncthreads();

#pragma unroll
        for (int c = 0; c < 64; ++c) {
            float4 pa = *(const float4*)&Pt[c * 64 + ty * 4];
            float4 vv = *(const float4*)&Vs[c * 64 + tx * 4];
            const float ra[4] = {pa.x, pa.y, pa.z, pa.w};
            const float rb[4] = {vv.x, vv.y, vv.z, vv.w};
#pragma unroll
            for (int i = 0; i < 4; ++i)
#pragma unroll
                for (int j = 0; j < 4; ++j)
                    acc[i][j] = fmaf(ra[i], rb[j], acc[i][j]);
        }
        __syncthreads();
    }

#pragma unroll
    for (int i = 0; i < 4; ++i) {
        const float inv = 1.0f / l_i[i];
        float* orow = O + (size_t)(b * TT + t0 + ty * 4 + i) * DD + h * HD + tx * 4;
        float4 o;
        o.x = acc[i][0] * inv;
        o.y = acc[i][1] * inv;
        o.z = acc[i][2] * inv;
        o.w = acc[i][3] * inv;
        *(float4*)orow = o;
    }
}

// ----------------------------------------------------------------------------
// Launch
// ----------------------------------------------------------------------------
extern "C" void kernel_launch(void* const* d_in, const int* in_sizes, int n_in,
                              void* d_out, int out_size)
{
    const float* dec = (const float*)d_in[0];   // [B,T,D]
    const float* enc = (const float*)d_in[1];   // [B,S,D]
    const float* Wq  = (const float*)d_in[2];
    const float* bq  = (const float*)d_in[3];
    const float* Wk  = (const float*)d_in[4];
    const float* bk  = (const float*)d_in[5];
    const float* Wv  = (const float*)d_in[6];
    const float* bv  = (const float*)d_in[7];
    const float* Wo  = (const float*)d_in[8];
    const float* bo  = (const float*)d_in[9];
    float* out = (float*)d_out;

    float *gQ, *gK, *gV, *gA;
    cudaGetSymbolAddress((void**)&gQ, g_Q);
    cudaGetSymbolAddress((void**)&gK, g_K);
    cudaGetSymbolAddress((void**)&gV, g_V);
    cudaGetSymbolAddress((void**)&gA, g_attn);

    static const int FA_SMEM = 4 * 64 * 64 * (int)sizeof(float);
    cudaFuncSetAttribute(flash_attn_kernel,
                         cudaFuncAttributeMaxDynamicSharedMemorySize, FA_SMEM);
    cudaFuncSetAttribute(gemm_tc_tf32_kernel,
                         cudaFuncAttributeMaxDynamicSharedMemorySize, GM_SMEM_BYTES);

    // Q projection: [B*T, D] = dec @ Wq^T + bq
    {
        dim3 grid(DD / GM_BN, (BB * TT) / GM_BM);
        gemm_tc_tf32_kernel<<<grid, 256, GM_SMEM_BYTES>>>(dec, Wq, bq, gQ, BB * TT, DD, DD);
    }
    // K projection: [B*S, D]
    {
        dim3 grid(DD / GM_BN, (BB * SS) / GM_BM);
        gemm_tc_tf32_kernel<<<grid, 256, GM_SMEM_BYTES>>>(enc, Wk, bk, gK, BB * SS, DD, DD);
    }
    // V projection: [B*S, D]
    {
        dim3 grid(DD / GM_BN, (BB * SS) / GM_BM);
        gemm_tc_tf32_kernel<<<grid, 256, GM_SMEM_BYTES>>>(enc, Wv, bv, gV, BB * SS, DD, DD);
    }
    // Attention
    {
        dim3 grid(TT / 64, BB * HH);
        flash_attn_kernel<<<grid, 256, FA_SMEM>>>(gQ, gK, gV, gA);
    }
    // Output projection: [B*T, D] = attn @ Wo^T + bo
    {
        dim3 grid(DD / GM_BN, (BB * TT) / GM_BM);
        gemm_tc_tf32_kernel<<<grid, 256, GM_SMEM_BYTES>>>(gA, Wo, bo, out, BB * TT, DD, DD);
    }
}

// round 4
// speedup vs baseline: 3.5109x; 2.1602x over previous
#include <cuda_runtime.h>
#include <cuda_bf16.h>
#include <math.h>
#include <stdint.h>

// ----------------------------------------------------------------------------
// Problem constants (fixed shapes)
// ----------------------------------------------------------------------------
#define BB   4
#define TT   1024
#define SS   4096
#define DD   1024
#define HH   16
#define HD   64

__constant__ int c_stride[HH] = {1,2,4,8, 1,2,4,8, 1,2,4,8, 1,2,4,8};
// heavy (stride-1) heads first in launch order
__constant__ int c_hmap[HH] = {0,4,8,12, 1,5,9,13, 2,6,10,14, 3,7,11,15};

// Scratch (device globals are the allowed scratch mechanism)
__device__ float g_Q[(size_t)BB * TT * DD];      // 16 MB
__device__ float g_K[(size_t)BB * SS * DD];      // 64 MB
__device__ float g_V[(size_t)BB * SS * DD];      // 64 MB
__device__ float g_attn[(size_t)BB * TT * DD];   // 16 MB

// ----------------------------------------------------------------------------
// Helpers (sm_100 baseline features only — NO 'a'-suffix instructions)
// ----------------------------------------------------------------------------
__device__ __forceinline__ uint32_t smem_u32(const void* p) {
    uint32_t a;
    asm("{ .reg .u64 t; cvta.to.shared.u64 t, %1; cvt.u32.u64 %0, t; }"
        : "=r"(a) : "l"(p));
    return a;
}
__device__ __forceinline__ uint32_t f2tf32(float x) {
    uint32_t o;
    asm("cvt.rna.tf32.f32 %0, %1;" : "=r"(o) : "f"(x));
    return o;
}
__device__ __forceinline__ void ldmatrix_x4(uint32_t* f, uint32_t addr) {
    asm volatile("ldmatrix.sync.aligned.m8n8.x4.shared.b16 {%0,%1,%2,%3}, [%4];"
                 : "=r"(f[0]), "=r"(f[1]), "=r"(f[2]), "=r"(f[3]) : "r"(addr));
}
__device__ __forceinline__ void mma_tf32(float* c, const uint32_t* a,
                                         uint32_t b0, uint32_t b1) {
    asm volatile(
        "mma.sync.aligned.m16n8k8.row.col.f32.tf32.tf32.f32 "
        "{%0,%1,%2,%3}, {%4,%5,%6,%7}, {%8,%9}, {%0,%1,%2,%3};"
        : "+f"(c[0]), "+f"(c[1]), "+f"(c[2]), "+f"(c[3])
        : "r"(a[0]), "r"(a[1]), "r"(a[2]), "r"(a[3]), "r"(b0), "r"(b1));
}

// ----------------------------------------------------------------------------
// Tensor-core tf32 GEMM:  C[M,N] = A[M,K] @ W[N,K]^T + bias[N]   (unchanged R3)
// ----------------------------------------------------------------------------
#define GM_BM 128
#define GM_BN 128
#define GM_BK 32
#define GM_TILE_BYTES  (128 * 128)
#define GM_STAGE_BYTES (2 * GM_TILE_BYTES)
#define GM_SMEM_BYTES  (2 * GM_STAGE_BYTES)

static __device__ __forceinline__ uint32_t tile_off(int row, int seg) {
    return (uint32_t)(row * 128 + ((seg ^ (row & 7)) << 4));
}

__global__ __launch_bounds__(256)
void gemm_tc_tf32_kernel(const float* __restrict__ A,
                         const float* __restrict__ W,
                         const float* __restrict__ bias,
                         float* __restrict__ C,
                         int M, int N, int K)
{
    extern __shared__ char sm_raw[];
    const uint32_t smBase = smem_u32(sm_raw);

    const int tid  = threadIdx.x;
    const int wid  = tid >> 5;
    const int lane = tid & 31;

    const int row0 = blockIdx.y * GM_BM;
    const int col0 = blockIdx.x * GM_BN;

    const int warp_m0 = (wid >> 2) * 64;
    const int warp_n0 = (wid & 3) * 32;

    const int rrow = (lane & 7) + (((lane >> 3) & 1) << 3);
    const int sadd = lane >> 4;

    const float* Ap = A + (size_t)row0 * K;
    const float* Wp = W + (size_t)col0 * K;

    float acc[4][4][4];
#pragma unroll
    for (int i = 0; i < 4; ++i)
#pragma unroll
        for (int j = 0; j < 4; ++j)
#pragma unroll
            for (int q = 0; q < 4; ++q) acc[i][j][q] = 0.f;

    const int l_row[4] = { (tid + 0)   >> 3, (tid + 256) >> 3,
                           (tid + 512) >> 3, (tid + 768) >> 3 };
    const int l_seg = tid & 7;

    auto sts_tile = [&](uint32_t tbase, const float4* r) {
#pragma unroll
        for (int it = 0; it < 4; ++it) {
            uint4 u;
            u.x = f2tf32(r[it].x); u.y = f2tf32(r[it].y);
            u.z = f2tf32(r[it].z); u.w = f2tf32(r[it].w);
            *(uint4*)(sm_raw + (tbase - smBase) + tile_off(l_row[it], l_seg)) = u;
        }
    };
    auto ldg_tile = [&](const float* g, int k0, float4* r) {
#pragma unroll
        for (int it = 0; it < 4; ++it)
            r[it] = *(const float4*)(g + (size_t)l_row[it] * K + k0 + l_seg * 4);
    };

    const int NCH = K / GM_BK;

    {
        float4 rA[4], rB[4];
        ldg_tile(Ap, 0, rA);
        ldg_tile(Wp, 0, rB);
        sts_tile(smBase, rA);
        sts_tile(smBase + GM_TILE_BYTES, rB);
    }
    __syncthreads();

    for (int c = 0; c < NCH; ++c) {
        const int s = c & 1;
        const uint32_t aBase = smBase + s * GM_STAGE_BYTES;
        const uint32_t bBase = aBase + GM_TILE_BYTES;

        float4 rA[4], rB[4];
        const bool pref = (c + 1 < NCH);
        if (pref) {
            ldg_tile(Ap, (c + 1) * GM_BK, rA);
            ldg_tile(Wp, (c + 1) * GM_BK, rB);
        }

#pragma unroll
        for (int k = 0; k < 4; ++k) {
            const int seg = k * 2 + sadd;
            uint32_t af[4][4], bf[2][4];
#pragma unroll
            for (int i = 0; i < 4; ++i) {
                const int row = warp_m0 + 16 * i + rrow;
                ldmatrix_x4(af[i], aBase + tile_off(row, seg));
            }
#pragma unroll
            for (int j = 0; j < 2; ++j) {
                const int row = warp_n0 + 16 * j + rrow;
                ldmatrix_x4(bf[j], bBase + tile_off(row, seg));
            }
#pragma unroll
            for (int i = 0; i < 4; ++i)
#pragma unroll
                for (int j = 0; j < 2; ++j) {
                    mma_tf32(acc[i][2 * j],     af[i], bf[j][0], bf[j][2]);
                    mma_tf32(acc[i][2 * j + 1], af[i], bf[j][1], bf[j][3]);
                }
        }

        if (pref) {
            const uint32_t a2 = smBase + (s ^ 1) * GM_STAGE_BYTES;
            sts_tile(a2, rA);
            sts_tile(a2 + GM_TILE_BYTES, rB);
        }
        __syncthreads();
    }

    {
        const int g = lane >> 2;
        const int t = lane & 3;
#pragma unroll
        for (int i = 0; i < 4; ++i) {
            const int r = row0 + warp_m0 + 16 * i + g;
#pragma unroll
            for (int jb = 0; jb < 4; ++jb) {
                const int cc = col0 + warp_n0 + 8 * jb + 2 * t;
                const float bx = __ldg(&bias[cc]);
                const float by = __ldg(&bias[cc + 1]);
                *(float2*)&C[(size_t)r * N + cc] =
                    make_float2(acc[i][jb][0] + bx, acc[i][jb][1] + by);
                *(float2*)&C[(size_t)(r + 8) * N + cc] =
                    make_float2(acc[i][jb][2] + bx, acc[i][jb][3] + by);
            }
        }
    }
}

// ----------------------------------------------------------------------------
// Tensor-core flash attention (tf32 mma), per-head strided K/V.
// CTA: 128 queries x one (b,h). 8 warps; warp w owns query rows [16w,16w+16).
// K tiles of 64 keys. Q pre-scaled by 1/8 and cvt to tf32 in smem.
// Smem (256B rows, XOR-swizzled 16B segs):
//   Qs 128x64 tf32 (32KB) | Ks 64x64 (16KB, key-major) |
//   Vt 64x64  (16KB, d-major = transposed) | Ps 128x64 (32KB)
// ----------------------------------------------------------------------------
#define FA_SMEM_BYTES (32768 + 16384 + 16384 + 32768)

static __device__ __forceinline__ uint32_t toff2(int row, int seg) {
    return (uint32_t)(row * 256 + ((seg ^ (row & 7)) << 4));
}

__global__ __launch_bounds__(256)
void flash_tc_kernel(const float* __restrict__ Q,
                     const float* __restrict__ K,
                     const float* __restrict__ V,
                     float* __restrict__ O)
{
    extern __shared__ char sm_raw[];
    const uint32_t QsB = smem_u32(sm_raw);
    const uint32_t KsB = QsB + 32768;
    const uint32_t VtB = KsB + 16384;
    const uint32_t PsB = VtB + 16384;

    const int tid  = threadIdx.x;
    const int wid  = tid >> 5;
    const int lane = tid & 31;

    const int y  = blockIdx.y;
    const int b  = y & 3;
    const int h  = c_hmap[y >> 2];
    const int stride = c_stride[h];
    const int t0 = blockIdx.x * 128;

    const int rrow = (lane & 7) + (((lane >> 3) & 1) << 3);
    const int sadd = lane >> 4;
    const int g    = lane >> 2;
    const int t    = lane & 3;
    const int w16  = wid * 16;

    // ---- load Q tile: 128 rows x 16 segs, scale by 1/8, cvt tf32 ----
    {
        const float* qb = Q + ((size_t)(b * TT + t0)) * DD + h * HD;
#pragma unroll
        for (int it = 0; it < 8; ++it) {
            const int idx = tid + it * 256;
            const int row = idx >> 4;
            const int seg = idx & 15;
            float4 v = *(const float4*)(qb + (size_t)row * DD + seg * 4);
            uint4 u;
            u.x = f2tf32(v.x * 0.125f); u.y = f2tf32(v.y * 0.125f);
            u.z = f2tf32(v.z * 0.125f); u.w = f2tf32(v.w * 0.125f);
            *(uint4*)(sm_raw + (QsB - QsB) + toff2(row, seg) + (KsB - KsB)) = u;  // placeholder
            *(uint4*)(sm_raw + toff2(row, seg)) = u;
        }
    }

    float m0 = -INFINITY, m1 = -INFINITY, l0 = 0.f, l1 = 0.f;
    float acc_o[8][4];
#pragma unroll
    for (int jb = 0; jb < 8; ++jb)
#pragma unroll
        for (int q = 0; q < 4; ++q) acc_o[jb][q] = 0.f;

    const int nTiles = SS / (stride * 64);

    for (int tile = 0; tile < nTiles; ++tile) {
        __syncthreads();   // Qs visible (1st iter); Ks/Vt fully consumed (later)

        // ---- load K tile: 64 rows(key) x 16 segs ----
        {
#pragma unroll
            for (int it = 0; it < 4; ++it) {
                const int idx = tid + it * 256;
                const int row = idx >> 4;
                const int seg = idx & 15;
                const int srow = (tile * 64 + row) * stride;
                float4 v = *(const float4*)(K + ((size_t)(b * SS + srow)) * DD + h * HD + seg * 4);
                uint4 u;
                u.x = f2tf32(v.x); u.y = f2tf32(v.y);
                u.z = f2tf32(v.z); u.w = f2tf32(v.w);
                *(uint4*)(sm_raw + (KsB - QsB) + toff2(row, seg)) = u;
            }
        }
        // ---- load V tile transposed: Vt[d][s] ----
        {
            const int s_loc = tid & 63;
            const int q0    = tid >> 6;
            const int srow  = (tile * 64 + s_loc) * stride;
            const float* vb = V + ((size_t)(b * SS + srow)) * DD + h * HD;
#pragma unroll
            for (int p = 0; p < 4; ++p) {
                const int q  = q0 + p * 4;
                const int d0 = q * 4;
                float4 v = *(const float4*)(vb + d0);
                const float vv[4] = {v.x, v.y, v.z, v.w};
#pragma unroll
                for (int e = 0; e < 4; ++e) {
                    const int d = d0 + e;
                    *(uint32_t*)(sm_raw + (VtB - QsB) + d * 256 +
                                 (((s_loc >> 2) ^ (d & 7)) << 4) + (s_loc & 3) * 4)
                        = f2tf32(vv[e]);
                }
            }
        }
        __syncthreads();

        // ---- S = Q @ K^T  (warp: 16 q-rows x 64 keys) ----
        float s[8][4];
#pragma unroll
        for (int jb = 0; jb < 8; ++jb)
#pragma unroll
            for (int q = 0; q < 4; ++q) s[jb][q] = 0.f;

#pragma unroll
        for (int k = 0; k < 8; ++k) {
            const int seg = k * 2 + sadd;
            uint32_t af[4];
            ldmatrix_x4(af, QsB + toff2(w16 + rrow, seg));
#pragma unroll
            for (int j = 0; j < 4; ++j) {
                uint32_t bf[4];
                ldmatrix_x4(bf, KsB + toff2(16 * j + rrow, seg));
                mma_tf32(s[2 * j],     af, bf[0], bf[2]);
                mma_tf32(s[2 * j + 1], af, bf[1], bf[3]);
            }
        }

        // ---- online softmax (rows g and g+8; 4 lanes t share a row) ----
        float tm0 = -INFINITY, tm1 = -INFINITY;
#pragma unroll
        for (int jb = 0; jb < 8; ++jb) {
            tm0 = fmaxf(tm0, fmaxf(s[jb][0], s[jb][1]));
            tm1 = fmaxf(tm1, fmaxf(s[jb][2], s[jb][3]));
        }
#pragma unroll
        for (int msk = 1; msk < 4; msk <<= 1) {
            tm0 = fmaxf(tm0, __shfl_xor_sync(0xffffffffu, tm0, msk));
            tm1 = fmaxf(tm1, __shfl_xor_sync(0xffffffffu, tm1, msk));
        }
        const float mn0 = fmaxf(m0, tm0);
        const float mn1 = fmaxf(m1, tm1);
        const float cr0 = __expf(m0 - mn0);
        const float cr1 = __expf(m1 - mn1);
        m0 = mn0; m1 = mn1;

        float sum0 = 0.f, sum1 = 0.f;
#pragma unroll
        for (int jb = 0; jb < 8; ++jb) {
            const float p0 = __expf(s[jb][0] - mn0);
            const float p1 = __expf(s[jb][1] - mn0);
            const float p2 = __expf(s[jb][2] - mn1);
            const float p3 = __expf(s[jb][3] - mn1);
            sum0 += p0 + p1;
            sum1 += p2 + p3;
            // store P (tf32) into Ps: rows w16+g / w16+g+8, col = jb*8 + 2t
            const int c0  = jb * 8 + 2 * t;
            const int seg = c0 >> 2;
            const int ofs = (c0 & 3) * 4;
            const int rA  = w16 + g;
            const int rB  = rA + 8;
            *(uint2*)(sm_raw + (PsB - QsB) + rA * 256 +
                      ((seg ^ (rA & 7)) << 4) + ofs) = make_uint2(f2tf32(p0), f2tf32(p1));
            *(uint2*)(sm_raw + (PsB - QsB) + rB * 256 +
                      ((seg ^ (rB & 7)) << 4) + ofs) = make_uint2(f2tf32(p2), f2tf32(p3));
        }
#pragma unroll
        for (int msk = 1; msk < 4; msk <<= 1) {
            sum0 += __shfl_xor_sync(0xffffffffu, sum0, msk);
            sum1 += __shfl_xor_sync(0xffffffffu, sum1, msk);
        }
        l0 = l0 * cr0 + sum0;
        l1 = l1 * cr1 + sum1;
#pragma unroll
        for (int jb = 0; jb < 8; ++jb) {
            acc_o[jb][0] *= cr0; acc_o[jb][1] *= cr0;
            acc_o[jb][2] *= cr1; acc_o[jb][3] *= cr1;
        }
        __syncwarp();

        // ---- O += P @ V  (A = Ps warp rows, B = Vt d-major) ----
#pragma unroll
        for (int k = 0; k < 8; ++k) {
            const int seg = k * 2 + sadd;
            uint32_t af[4];
            ldmatrix_x4(af, PsB + toff2(w16 + rrow, seg));
#pragma unroll
            for (int j = 0; j < 4; ++j) {
                uint32_t bf[4];
                ldmatrix_x4(bf, VtB + toff2(16 * j + rrow, seg));
                mma_tf32(acc_o[2 * j],     af, bf[0], bf[2]);
                mma_tf32(acc_o[2 * j + 1], af, bf[1], bf[3]);
            }
        }
    }

    // ---- epilogue ----
    {
        const float inv0 = 1.0f / l0;
        const float inv1 = 1.0f / l1;
        const int r0 = t0 + w16 + g;
        const int r1 = r0 + 8;
#pragma unroll
        for (int jb = 0; jb < 8; ++jb) {
            const int d = jb * 8 + 2 * t;
            *(float2*)&O[((size_t)(b * TT + r0)) * DD + h * HD + d] =
                make_float2(acc_o[jb][0] * inv0, acc_o[jb][1] * inv0);
            *(float2*)&O[((size_t)(b * TT + r1)) * DD + h * HD + d] =
                make_float2(acc_o[jb][2] * inv1, acc_o[jb][3] * inv1);
        }
    }
}

// ----------------------------------------------------------------------------
// Launch
// ----------------------------------------------------------------------------
extern "C" void kernel_launch(void* const* d_in, const int* in_sizes, int n_in,
                              void* d_out, int out_size)
{
    const float* dec = (const float*)d_in[0];   // [B,T,D]
    const float* enc = (const float*)d_in[1];   // [B,S,D]
    const float* Wq  = (const float*)d_in[2];
    const float* bq  = (const float*)d_in[3];
    const float* Wk  = (const float*)d_in[4];
    const float* bk  = (const float*)d_in[5];
    const float* Wv  = (const float*)d_in[6];
    const float* bv  = (const float*)d_in[7];
    const float* Wo  = (const float*)d_in[8];
    const float* bo  = (const float*)d_in[9];
    float* out = (float*)d_out;

    float *gQ, *gK, *gV, *gA;
    cudaGetSymbolAddress((void**)&gQ, g_Q);
    cudaGetSymbolAddress((void**)&gK, g_K);
    cudaGetSymbolAddress((void**)&gV, g_V);
    cudaGetSymbolAddress((void**)&gA, g_attn);

    cudaFuncSetAttribute(gemm_tc_tf32_kernel,
                         cudaFuncAttributeMaxDynamicSharedMemorySize, GM_SMEM_BYTES);
    cudaFuncSetAttribute(flash_tc_kernel,
                         cudaFuncAttributeMaxDynamicSharedMemorySize, FA_SMEM_BYTES);

    // Q projection: [B*T, D] = dec @ Wq^T + bq
    {
        dim3 grid(DD / GM_BN, (BB * TT) / GM_BM);
        gemm_tc_tf32_kernel<<<grid, 256, GM_SMEM_BYTES>>>(dec, Wq, bq, gQ, BB * TT, DD, DD);
    }
    // K projection: [B*S, D]
    {
        dim3 grid(DD / GM_BN, (BB * SS) / GM_BM);
        gemm_tc_tf32_kernel<<<grid, 256, GM_SMEM_BYTES>>>(enc, Wk, bk, gK, BB * SS, DD, DD);
    }
    // V projection: [B*S, D]
    {
        dim3 grid(DD / GM_BN, (BB * SS) / GM_BM);
        gemm_tc_tf32_kernel<<<grid, 256, GM_SMEM_BYTES>>>(enc, Wv, bv, gV, BB * SS, DD, DD);
    }
    // Attention (tensor-core flash)
    {
        dim3 grid(TT / 128, BB * HH);
        flash_tc_kernel<<<grid, 256, FA_SMEM_BYTES>>>(gQ, gK, gV, gA);
    }
    // Output projection: [B*T, D] = attn @ Wo^T + bo
    {
        dim3 grid(DD / GM_BN, (BB * TT) / GM_BM);
        gemm_tc_tf32_kernel<<<grid, 256, GM_SMEM_BYTES>>>(gA, Wo, bo, out, BB * TT, DD, DD);
    }
}

// round 5
// speedup vs baseline: 4.1040x; 1.1689x over previous
#include <cuda_runtime.h>
#include <cuda_bf16.h>
#include <math.h>
#include <stdint.h>

// ----------------------------------------------------------------------------
// Problem constants (fixed shapes)
// ----------------------------------------------------------------------------
#define BB   4
#define TT   1024
#define SS   4096
#define DD   1024
#define HH   16
#define HD   64

__constant__ int c_stride[HH] = {1,2,4,8, 1,2,4,8, 1,2,4,8, 1,2,4,8};
// heavy (stride-1) heads first in launch order
__constant__ int c_hmap[HH] = {0,4,8,12, 1,5,9,13, 2,6,10,14, 3,7,11,15};

// Scratch (device globals are the allowed scratch mechanism)
__device__ float g_Q[(size_t)BB * TT * DD];      // 16 MB
__device__ float g_K[(size_t)BB * SS * DD];      // 64 MB
__device__ float g_V[(size_t)BB * SS * DD];      // 64 MB
__device__ float g_attn[(size_t)BB * TT * DD];   // 16 MB
// tf32-prerounded copies of inputs
__device__ float g_decT[(size_t)BB * TT * DD];   // 16 MB
__device__ float g_encT[(size_t)BB * SS * DD];   // 64 MB
__device__ float g_Wq[(size_t)DD * DD];
__device__ float g_Wk[(size_t)DD * DD];
__device__ float g_Wv[(size_t)DD * DD];
__device__ float g_Wo[(size_t)DD * DD];

// ----------------------------------------------------------------------------
// Helpers (sm_100 baseline features only — NO 'a'-suffix instructions)
// ----------------------------------------------------------------------------
__device__ __forceinline__ uint32_t smem_u32(const void* p) {
    uint32_t a;
    asm("{ .reg .u64 t; cvta.to.shared.u64 t, %1; cvt.u32.u64 %0, t; }"
        : "=r"(a) : "l"(p));
    return a;
}
__device__ __forceinline__ uint32_t f2tf32(float x) {
    uint32_t o;
    asm("cvt.rna.tf32.f32 %0, %1;" : "=r"(o) : "f"(x));
    return o;
}
__device__ __forceinline__ void ldmatrix_x4(uint32_t* f, uint32_t addr) {
    asm volatile("ldmatrix.sync.aligned.m8n8.x4.shared.b16 {%0,%1,%2,%3}, [%4];"
                 : "=r"(f[0]), "=r"(f[1]), "=r"(f[2]), "=r"(f[3]) : "r"(addr));
}
__device__ __forceinline__ void mma_tf32(float* c, const uint32_t* a,
                                         uint32_t b0, uint32_t b1) {
    asm volatile(
        "mma.sync.aligned.m16n8k8.row.col.f32.tf32.tf32.f32 "
        "{%0,%1,%2,%3}, {%4,%5,%6,%7}, {%8,%9}, {%0,%1,%2,%3};"
        : "+f"(c[0]), "+f"(c[1]), "+f"(c[2]), "+f"(c[3])
        : "r"(a[0]), "r"(a[1]), "r"(a[2]), "r"(a[3]), "r"(b0), "r"(b1));
}
__device__ __forceinline__ void cp16(uint32_t saddr, const void* g) {
    asm volatile("cp.async.cg.shared.global [%0], [%1], 16;"
                 :: "r"(saddr), "l"(g) : "memory");
}
#define CP_COMMIT() asm volatile("cp.async.commit_group;" ::: "memory")
#define CP_WAIT(n)  asm volatile("cp.async.wait_group %0;" :: "n"(n) : "memory")

// ----------------------------------------------------------------------------
// Pre-round pass: dst[i] = tf32_rna(src[i])
// ----------------------------------------------------------------------------
__global__ void round_tf32_kernel(const float* __restrict__ src,
                                  float* __restrict__ dst, int n4)
{
    int i = blockIdx.x * blockDim.x + threadIdx.x;
    if (i < n4) {
        float4 v = ((const float4*)src)[i];
        uint4 u;
        u.x = f2tf32(v.x); u.y = f2tf32(v.y);
        u.z = f2tf32(v.z); u.w = f2tf32(v.w);
        ((uint4*)dst)[i] = u;
    }
}

// ----------------------------------------------------------------------------
// Tensor-core tf32 GEMM core:  C[128,128] tile of A[M,K] @ W[N,K]^T + bias
// cp.async 3-stage pipeline, BK=32, 8 warps 2(m)x4(n), warp tile 64x32.
// Inputs already tf32-rounded. Optionally round outputs.
// ----------------------------------------------------------------------------
#define GM_BK 32
#define GM_TILE_BYTES  (128 * 128)               // 128 rows x 128B
#define GM_STAGE_BYTES (2 * GM_TILE_BYTES)       // A + B
#define GM_SMEM_BYTES  (3 * GM_STAGE_BYTES)      // 96KB

static __device__ __forceinline__ uint32_t tile_off(int row, int seg) {
    return (uint32_t)(row * 128 + ((seg ^ (row & 7)) << 4));
}

template<bool ROUND>
__device__ __forceinline__ void gemm_core(const float* __restrict__ A,
                                          const float* __restrict__ W,
                                          const float* __restrict__ bias,
                                          float* __restrict__ C,
                                          int mt, int nt)
{
    extern __shared__ char sm_raw[];
    const uint32_t smBase = smem_u32(sm_raw);
    const int K = DD, N = DD;

    const int tid  = threadIdx.x;
    const int wid  = tid >> 5;
    const int lane = tid & 31;

    const int row0 = mt * 128;
    const int col0 = nt * 128;

    const int warp_m0 = (wid >> 2) * 64;
    const int warp_n0 = (wid & 3) * 32;
    const int rrow = (lane & 7) + (((lane >> 3) & 1) << 3);
    const int sadd = lane >> 4;

    const float* Ap = A + (size_t)row0 * K;
    const float* Wp = W + (size_t)col0 * K;

    const int l_row = tid >> 3;       // 0..31 (32 rows per pass, 4 passes)
    const int l_seg = tid & 7;

    auto issue = [&](int c, int s) {
        const uint32_t sa = smBase + s * GM_STAGE_BYTES;
        const float* ga = Ap + c * GM_BK;
        const float* gb = Wp + c * GM_BK;
#pragma unroll
        for (int it = 0; it < 4; ++it) {
            const int row = l_row + it * 32;
            cp16(sa + tile_off(row, l_seg), ga + (size_t)row * K + l_seg * 4);
        }
#pragma unroll
        for (int it = 0; it < 4; ++it) {
            const int row = l_row + it * 32;
            cp16(sa + GM_TILE_BYTES + tile_off(row, l_seg),
                 gb + (size_t)row * K + l_seg * 4);
        }
        CP_COMMIT();
    };

    float acc[4][4][4];
#pragma unroll
    for (int i = 0; i < 4; ++i)
#pragma unroll
        for (int j = 0; j < 4; ++j)
#pragma unroll
            for (int q = 0; q < 4; ++q) acc[i][j][q] = 0.f;

    const int NCH = K / GM_BK;   // 32
    issue(0, 0);
    issue(1, 1);

    for (int c = 0; c < NCH; ++c) {
        const int s = c % 3;
        CP_WAIT(1);
        __syncthreads();
        if (c + 2 < NCH) issue(c + 2, (c + 2) % 3);

        const uint32_t aBase = smBase + s * GM_STAGE_BYTES;
        const uint32_t bBase = aBase + GM_TILE_BYTES;
#pragma unroll
        for (int k = 0; k < 4; ++k) {
            const int seg = k * 2 + sadd;
            uint32_t af[4][4], bf[2][4];
#pragma unroll
            for (int i = 0; i < 4; ++i)
                ldmatrix_x4(af[i], aBase + tile_off(warp_m0 + 16 * i + rrow, seg));
#pragma unroll
            for (int j = 0; j < 2; ++j)
                ldmatrix_x4(bf[j], bBase + tile_off(warp_n0 + 16 * j + rrow, seg));
#pragma unroll
            for (int i = 0; i < 4; ++i)
#pragma unroll
                for (int j = 0; j < 2; ++j) {
                    mma_tf32(acc[i][2 * j],     af[i], bf[j][0], bf[j][2]);
                    mma_tf32(acc[i][2 * j + 1], af[i], bf[j][1], bf[j][3]);
                }
        }
        __syncthreads();
    }

    // epilogue
    {
        const int g = lane >> 2;
        const int t = lane & 3;
#pragma unroll
        for (int i = 0; i < 4; ++i) {
            const int r = row0 + warp_m0 + 16 * i + g;
#pragma unroll
            for (int jb = 0; jb < 4; ++jb) {
                const int cc = col0 + warp_n0 + 8 * jb + 2 * t;
                const float bx = __ldg(&bias[cc]);
                const float by = __ldg(&bias[cc + 1]);
                float o0 = acc[i][jb][0] + bx, o1 = acc[i][jb][1] + by;
                float o2 = acc[i][jb][2] + bx, o3 = acc[i][jb][3] + by;
                if (ROUND) {
                    o0 = __uint_as_float(f2tf32(o0));
                    o1 = __uint_as_float(f2tf32(o1));
                    o2 = __uint_as_float(f2tf32(o2));
                    o3 = __uint_as_float(f2tf32(o3));
                }
                *(float2*)&C[(size_t)r * N + cc]       = make_float2(o0, o1);
                *(float2*)&C[(size_t)(r + 8) * N + cc] = make_float2(o2, o3);
            }
        }
    }
}

// Fused Q/K/V projections: 2304 CTAs (256 Q + 1024 K + 1024 V)
__global__ __launch_bounds__(256, 2)
void gemm_qkv_kernel(const float* __restrict__ decT, const float* __restrict__ encT,
                     const float* __restrict__ Wq, const float* __restrict__ Wk,
                     const float* __restrict__ Wv,
                     const float* __restrict__ bq, const float* __restrict__ bk,
                     const float* __restrict__ bv,
                     float* __restrict__ Qo, float* __restrict__ Ko,
                     float* __restrict__ Vo)
{
    int id = blockIdx.x;
    const float *A, *W, *bias;
    float* C;
    if (id < 256)        { A = decT; W = Wq; bias = bq; C = Qo; }
    else if (id < 1280)  { A = encT; W = Wk; bias = bk; C = Ko; id -= 256; }
    else                 { A = encT; W = Wv; bias = bv; C = Vo; id -= 1280; }
    gemm_core<true>(A, W, bias, C, id >> 3, id & 7);
}

// Output projection (plain fp32 output)
__global__ __launch_bounds__(256, 2)
void gemm_o_kernel(const float* __restrict__ A, const float* __restrict__ W,
                   const float* __restrict__ bias, float* __restrict__ C)
{
    gemm_core<false>(A, W, bias, C, blockIdx.y, blockIdx.x);
}

// ----------------------------------------------------------------------------
// Tensor-core flash attention v2 (tf32 mma), per-head strided K/V.
// CTA: 64 queries x one (b,h); 128 threads (4 warps), warp w -> rows [16w,16w+16).
// K/V tiles of 64 keys. All inputs pre-rounded tf32; Q/K via cp.async.
// Smem (256B rows, XOR-swizzled 16B segs):
//   Qs 64x64 (16KB) | Ks 64x64 (16KB) | Vt 64x64 d-major (16KB) | Ps 64x64 (16KB)
// ----------------------------------------------------------------------------
#define FA_SMEM_BYTES (4 * 16384)

static __device__ __forceinline__ uint32_t toff2(int row, int seg) {
    return (uint32_t)(row * 256 + ((seg ^ (row & 7)) << 4));
}

__global__ __launch_bounds__(128, 3)
void flash_tc_kernel(const float* __restrict__ Q,
                     const float* __restrict__ K,
                     const float* __restrict__ V,
                     float* __restrict__ O)
{
    extern __shared__ char sm_raw[];
    const uint32_t QsB = smem_u32(sm_raw);
    const uint32_t KsB = QsB + 16384;
    const uint32_t VtB = KsB + 16384;
    const uint32_t PsB = VtB + 16384;

    const int tid  = threadIdx.x;
    const int wid  = tid >> 5;
    const int lane = tid & 31;

    const int y  = blockIdx.y;
    const int b  = y & 3;
    const int h  = c_hmap[y >> 2];
    const int stride = c_stride[h];
    const int t0 = blockIdx.x * 64;

    const int rrow = (lane & 7) + (((lane >> 3) & 1) << 3);
    const int sadd = lane >> 4;
    const int g    = lane >> 2;
    const int t    = lane & 3;
    const int w16  = wid * 16;

    // fold attention scale into base-2 exponent units
    const float C1 = 0.125f * 1.4426950408889634f;

    // ---- Q tile via cp.async: 64 rows x 16 segs = 1024 chunks / 128 thr = 8 ----
    {
        const float* qb = Q + ((size_t)(b * TT + t0)) * DD + h * HD;
        const int row = tid >> 4;      // 0..7 (+8 per pass)
        const int seg = tid & 15;
#pragma unroll
        for (int it = 0; it < 8; ++it) {
            const int r = row + it * 8;
            cp16(QsB + toff2(r, seg), qb + (size_t)r * DD + seg * 4);
        }
        CP_COMMIT();
    }

    float m0 = -INFINITY, m1 = -INFINITY, l0 = 0.f, l1 = 0.f;
    float acc_o[8][4];
#pragma unroll
    for (int jb = 0; jb < 8; ++jb)
#pragma unroll
        for (int q = 0; q < 4; ++q) acc_o[jb][q] = 0.f;

    const int nTiles = SS / (stride * 64);
    const int s_loc = tid & 63;        // V loader: key index
    const int dh    = (tid >> 6) * 32; // V loader: d half

    for (int tile = 0; tile < nTiles; ++tile) {
        __syncthreads();   // previous tile's Ks/Vt fully consumed

        // ---- K tile via cp.async ----
        {
            const int row = tid >> 4;
            const int seg = tid & 15;
#pragma unroll
            for (int it = 0; it < 8; ++it) {
                const int r = row + it * 8;
                const int srow = (tile * 64 + r) * stride;
                cp16(KsB + toff2(r, seg),
                     K + ((size_t)(b * SS + srow)) * DD + h * HD + seg * 4);
            }
            CP_COMMIT();
        }
        // ---- V tile transposed via LDG + scattered STS ----
        {
            const int srow = (tile * 64 + s_loc) * stride;
            const float* vb = V + ((size_t)(b * SS + srow)) * DD + h * HD + dh;
#pragma unroll
            for (int p = 0; p < 8; ++p) {
                float4 v = *(const float4*)(vb + p * 4);
                const float vv[4] = {v.x, v.y, v.z, v.w};
#pragma unroll
                for (int e = 0; e < 4; ++e) {
                    const int d = dh + p * 4 + e;
                    *(float*)(sm_raw + (VtB - QsB) + d * 256 +
                              (((s_loc >> 2) ^ (d & 7)) << 4) + (s_loc & 3) * 4)
                        = vv[e];
                }
            }
        }
        CP_WAIT(0);
        __syncthreads();

        // ---- S = Q @ K^T  (warp: 16 q-rows x 64 keys) ----
        float s[8][4];
#pragma unroll
        for (int jb = 0; jb < 8; ++jb)
#pragma unroll
            for (int q = 0; q < 4; ++q) s[jb][q] = 0.f;

#pragma unroll
        for (int k = 0; k < 8; ++k) {
            const int seg = k * 2 + sadd;
            uint32_t af[4];
            ldmatrix_x4(af, QsB + toff2(w16 + rrow, seg));
#pragma unroll
            for (int j = 0; j < 4; ++j) {
                uint32_t bf[4];
                ldmatrix_x4(bf, KsB + toff2(16 * j + rrow, seg));
                mma_tf32(s[2 * j],     af, bf[0], bf[2]);
                mma_tf32(s[2 * j + 1], af, bf[1], bf[3]);
            }
        }
        // convert to base-2 scaled scores
#pragma unroll
        for (int jb = 0; jb < 8; ++jb)
#pragma unroll
            for (int q = 0; q < 4; ++q) s[jb][q] *= C1;

        // ---- online softmax (rows g and g+8; 4 lanes t share a row) ----
        float tm0 = -INFINITY, tm1 = -INFINITY;
#pragma unroll
        for (int jb = 0; jb < 8; ++jb) {
            tm0 = fmaxf(tm0, fmaxf(s[jb][0], s[jb][1]));
            tm1 = fmaxf(tm1, fmaxf(s[jb][2], s[jb][3]));
        }
#pragma unroll
        for (int msk = 1; msk < 4; msk <<= 1) {
            tm0 = fmaxf(tm0, __shfl_xor_sync(0xffffffffu, tm0, msk));
            tm1 = fmaxf(tm1, __shfl_xor_sync(0xffffffffu, tm1, msk));
        }
        const float mn0 = fmaxf(m0, tm0);
        const float mn1 = fmaxf(m1, tm1);
        const float cr0 = exp2f(m0 - mn0);
        const float cr1 = exp2f(m1 - mn1);
        m0 = mn0; m1 = mn1;

        float sum0 = 0.f, sum1 = 0.f;
#pragma unroll
        for (int jb = 0; jb < 8; ++jb) {
            const float p0 = exp2f(s[jb][0] - mn0);
            const float p1 = exp2f(s[jb][1] - mn0);
            const float p2 = exp2f(s[jb][2] - mn1);
            const float p3 = exp2f(s[jb][3] - mn1);
            sum0 += p0 + p1;
            sum1 += p2 + p3;
            const int c0  = jb * 8 + 2 * t;
            const int seg = c0 >> 2;
            const int ofs = (c0 & 3) * 4;
            const int rA  = w16 + g;
            const int rB  = rA + 8;
            *(uint2*)(sm_raw + (PsB - QsB) + rA * 256 +
                      ((seg ^ (rA & 7)) << 4) + ofs) = make_uint2(f2tf32(p0), f2tf32(p1));
            *(uint2*)(sm_raw + (PsB - QsB) + rB * 256 +
                      ((seg ^ (rB & 7)) << 4) + ofs) = make_uint2(f2tf32(p2), f2tf32(p3));
        }
#pragma unroll
        for (int msk = 1; msk < 4; msk <<= 1) {
            sum0 += __shfl_xor_sync(0xffffffffu, sum0, msk);
            sum1 += __shfl_xor_sync(0xffffffffu, sum1, msk);
        }
        l0 = l0 * cr0 + sum0;
        l1 = l1 * cr1 + sum1;
#pragma unroll
        for (int jb = 0; jb < 8; ++jb) {
            acc_o[jb][0] *= cr0; acc_o[jb][1] *= cr0;
            acc_o[jb][2] *= cr1; acc_o[jb][3] *= cr1;
        }
        __syncwarp();

        // ---- O += P @ V ----
#pragma unroll
        for (int k = 0; k < 8; ++k) {
            const int seg = k * 2 + sadd;
            uint32_t af[4];
            ldmatrix_x4(af, PsB + toff2(w16 + rrow, seg));
#pragma unroll
            for (int j = 0; j < 4; ++j) {
                uint32_t bf[4];
                ldmatrix_x4(bf, VtB + toff2(16 * j + rrow, seg));
                mma_tf32(acc_o[2 * j],     af, bf[0], bf[2]);
                mma_tf32(acc_o[2 * j + 1], af, bf[1], bf[3]);
            }
        }
    }

    // ---- epilogue: normalize, round to tf32 (O-proj consumes raw) ----
    {
        const float inv0 = 1.0f / l0;
        const float inv1 = 1.0f / l1;
        const int r0 = t0 + w16 + g;
        const int r1 = r0 + 8;
#pragma unroll
        for (int jb = 0; jb < 8; ++jb) {
            const int d = jb * 8 + 2 * t;
            uint2 u0 = make_uint2(f2tf32(acc_o[jb][0] * inv0),
                                  f2tf32(acc_o[jb][1] * inv0));
            uint2 u1 = make_uint2(f2tf32(acc_o[jb][2] * inv1),
                                  f2tf32(acc_o[jb][3] * inv1));
            *(uint2*)&O[((size_t)(b * TT + r0)) * DD + h * HD + d] = u0;
            *(uint2*)&O[((size_t)(b * TT + r1)) * DD + h * HD + d] = u1;
        }
    }
}

// ----------------------------------------------------------------------------
// Launch
// ----------------------------------------------------------------------------
extern "C" void kernel_launch(void* const* d_in, const int* in_sizes, int n_in,
                              void* d_out, int out_size)
{
    const float* dec = (const float*)d_in[0];   // [B,T,D]
    const float* enc = (const float*)d_in[1];   // [B,S,D]
    const float* Wq  = (const float*)d_in[2];
    const float* bq  = (const float*)d_in[3];
    const float* Wk  = (const float*)d_in[4];
    const float* bk  = (const float*)d_in[5];
    const float* Wv  = (const float*)d_in[6];
    const float* bv  = (const float*)d_in[7];
    const float* Wo  = (const float*)d_in[8];
    const float* bo  = (const float*)d_in[9];
    float* out = (float*)d_out;

    float *gQ, *gK, *gV, *gA, *gDec, *gEnc, *gWq, *gWk, *gWv, *gWo;
    cudaGetSymbolAddress((void**)&gQ,   g_Q);
    cudaGetSymbolAddress((void**)&gK,   g_K);
    cudaGetSymbolAddress((void**)&gV,   g_V);
    cudaGetSymbolAddress((void**)&gA,   g_attn);
    cudaGetSymbolAddress((void**)&gDec, g_decT);
    cudaGetSymbolAddress((void**)&gEnc, g_encT);
    cudaGetSymbolAddress((void**)&gWq,  g_Wq);
    cudaGetSymbolAddress((void**)&gWk,  g_Wk);
    cudaGetSymbolAddress((void**)&gWv,  g_Wv);
    cudaGetSymbolAddress((void**)&gWo,  g_Wo);

    cudaFuncSetAttribute(gemm_qkv_kernel,
                         cudaFuncAttributeMaxDynamicSharedMemorySize, GM_SMEM_BYTES);
    cudaFuncSetAttribute(gemm_o_kernel,
                         cudaFuncAttributeMaxDynamicSharedMemorySize, GM_SMEM_BYTES);
    cudaFuncSetAttribute(flash_tc_kernel,
                         cudaFuncAttributeMaxDynamicSharedMemorySize, FA_SMEM_BYTES);

    // ---- pre-round inputs to tf32 ----
    {
        const int nDec = BB * TT * DD / 4, nEnc = BB * SS * DD / 4, nW = DD * DD / 4;
        round_tf32_kernel<<<(nDec + 255) / 256, 256>>>(dec, gDec, nDec);
        round_tf32_kernel<<<(nEnc + 255) / 256, 256>>>(enc, gEnc, nEnc);
        round_tf32_kernel<<<(nW   + 255) / 256, 256>>>(Wq,  gWq,  nW);
        round_tf32_kernel<<<(nW   + 255) / 256, 256>>>(Wk,  gWk,  nW);
        round_tf32_kernel<<<(nW   + 255) / 256, 256>>>(Wv,  gWv,  nW);
        round_tf32_kernel<<<(nW   + 255) / 256, 256>>>(Wo,  gWo,  nW);
    }

    // ---- fused Q/K/V projections ----
    gemm_qkv_kernel<<<2304, 256, GM_SMEM_BYTES>>>(gDec, gEnc, gWq, gWk, gWv,
                                                  bq, bk, bv, gQ, gK, gV);

    // ---- attention ----
    {
        dim3 grid(TT / 64, BB * HH);
        flash_tc_kernel<<<grid, 128, FA_SMEM_BYTES>>>(gQ, gK, gV, gA);
    }

    // ---- output projection ----
    {
        dim3 grid(DD / 128, (BB * TT) / 128);
        gemm_o_kernel<<<grid, 256, GM_SMEM_BYTES>>>(gA, gWo, bo, out);
    }
}